// round 1
// baseline (speedup 1.0000x reference)
#include <cuda_runtime.h>

// ---------------------------------------------------------------------------
// SchNet fused kernel: 1 CTA per batch element, everything in SMEM.
//   r:(512,192) -> out:(512,1)
//   N_ATOMS=64, N_FEA=64, N_RBF=64, P=4032 pairs, 3 interaction blocks.
// ---------------------------------------------------------------------------

#define NPAD 65   // padded row stride (floats) -> conflict-free strided LDS

// shared memory layout (float offsets)
#define OFF_POS   0                         // 192
#define OFF_CEN   192                       // 64
#define OFF_D     256                       // 64*64   distances d[i*64+m]
#define OFF_X     (256 + 4096)              // 64*NPAD
#define OFF_XL    (OFF_X  + 64*NPAD)
#define OFF_VS    (OFF_XL + 64*NPAD)
#define OFF_WA    (OFF_VS + 64*NPAD)        // 64*64 weight A
#define OFF_WB    (OFF_WA + 4096)           // 64*64 weight B
#define OFF_TA    (OFF_WB + 4096)           // 128*NPAD tile A
#define OFF_TB    (OFF_TA + 128*NPAD)       // 128*NPAD tile B
#define OFF_RED   (OFF_TB + 128*NPAD)       // 256 reduction scratch
#define SMEM_FLOATS (OFF_RED + 256)
#define SMEM_BYTES  (SMEM_FLOATS * 4)       // 167680 bytes

__device__ __forceinline__ float fast_tanh(float x) {
    // tanh(x) = 1 - 2/(exp(2x)+1); exact at +-inf saturations, ~1e-6 abs err
    float e = __expf(2.0f * x);
    return 1.0f - __fdividef(2.0f, e + 1.0f);
}

// copy 4096 floats global->smem with 256 threads (float4)
__device__ __forceinline__ void load_w64(const float* __restrict__ g,
                                         float* __restrict__ s, int tid) {
    const float4* src = reinterpret_cast<const float4*>(g);
    float4*       dst = reinterpret_cast<float4*>(s);
#pragma unroll
    for (int k = 0; k < 4; k++) dst[tid + 256 * k] = src[tid + 256 * k];
}

// C[16R x 64] = epi(A[16R x 64 (ld NPAD)] @ W[64x64] + bias)
// EPI: 0 = none, 1 = tanh, 2 = add-into-C
template <int R, int EPI>
__device__ __forceinline__ void gemm_nn(const float* __restrict__ A,
                                        const float* __restrict__ W,
                                        const float* __restrict__ bias,
                                        float* __restrict__ C, int tid) {
    const int rg = tid >> 4;          // 0..15
    const int c0 = (tid & 15) * 4;    // 0..60

    float bb0 = __ldg(bias + c0 + 0);
    float bb1 = __ldg(bias + c0 + 1);
    float bb2 = __ldg(bias + c0 + 2);
    float bb3 = __ldg(bias + c0 + 3);

    float acc[R][4];
#pragma unroll
    for (int r = 0; r < R; r++) {
        acc[r][0] = bb0; acc[r][1] = bb1; acc[r][2] = bb2; acc[r][3] = bb3;
    }

#pragma unroll 4
    for (int k = 0; k < 64; k++) {
        float4 w = *reinterpret_cast<const float4*>(W + k * 64 + c0);
#pragma unroll
        for (int r = 0; r < R; r++) {
            float a = A[(rg + 16 * r) * NPAD + k];
            acc[r][0] = fmaf(a, w.x, acc[r][0]);
            acc[r][1] = fmaf(a, w.y, acc[r][1]);
            acc[r][2] = fmaf(a, w.z, acc[r][2]);
            acc[r][3] = fmaf(a, w.w, acc[r][3]);
        }
    }

#pragma unroll
    for (int r = 0; r < R; r++) {
        float* cp = C + (rg + 16 * r) * NPAD + c0;
#pragma unroll
        for (int j = 0; j < 4; j++) {
            float v = acc[r][j];
            if (EPI == 1) v = fast_tanh(v);
            if (EPI == 2) v += cp[j];
            cp[j] = v;
        }
    }
}

__global__ void __launch_bounds__(256, 1)
schnet_kernel(const float* __restrict__ r_g,
              const float* __restrict__ v1_g,
              const float* __restrict__ v2_g,
              const float* __restrict__ cen_g,
              const float* __restrict__ Wx_g,  const float* __restrict__ bx_g,
              const float* __restrict__ Wf1_g, const float* __restrict__ bf1_g,
              const float* __restrict__ Wf2_g, const float* __restrict__ bf2_g,
              const float* __restrict__ Wv1_g, const float* __restrict__ bv1_g,
              const float* __restrict__ Wv2_g, const float* __restrict__ bv2_g,
              const float* __restrict__ W1_g,  const float* __restrict__ b1_g,
              const float* __restrict__ W2_g,  const float* __restrict__ b2_g,
              float* __restrict__ out_g) {
    extern __shared__ float sm[];
    float* pos = sm + OFF_POS;
    float* cen = sm + OFF_CEN;
    float* d   = sm + OFF_D;
    float* X   = sm + OFF_X;
    float* Xl  = sm + OFF_XL;
    float* vs  = sm + OFF_VS;
    float* Wa  = sm + OFF_WA;
    float* Wb  = sm + OFF_WB;
    float* tA  = sm + OFF_TA;
    float* tB  = sm + OFF_TB;
    float* red = sm + OFF_RED;

    const int tid = threadIdx.x;
    const int b   = blockIdx.x;

    // ---- init: positions, rbf centers, atom embeddings ----
    if (tid < 192) pos[tid] = r_g[b * 192 + tid];
    if (tid < 64)  cen[tid] = cen_g[tid];
    for (int idx = tid; idx < 4096; idx += 256) {
        int a = idx >> 6, f = idx & 63;
        X[a * NPAD + f] = (a < 2) ? __ldg(v1_g + f) : __ldg(v2_g + f);
    }
    __syncthreads();

    // ---- pairwise distances (computed once, reused for all 3 interactions)
    for (int p = tid; p < 4032; p += 256) {
        int i = p / 63;
        int m = p - i * 63;
        int j = m + (m >= i);
        float dx = pos[3 * i + 0] - pos[3 * j + 0];
        float dy = pos[3 * i + 1] - pos[3 * j + 1];
        float dz = pos[3 * i + 2] - pos[3 * j + 2];
        d[i * 64 + m] = sqrtf(fmaf(dx, dx, fmaf(dy, dy, dz * dz)));
    }
    __syncthreads();

    // ---- 3 interaction blocks ----
    for (int t = 0; t < 3; t++) {
        const int wofs = t * 4096, bofs = t * 64;

        // Xl = X @ Wx[t] + bx[t]
        load_w64(Wx_g + wofs, Wa, tid);
        for (int idx = tid; idx < 64 * NPAD; idx += 256) vs[idx] = 0.0f;
        __syncthreads();
        gemm_nn<4, 0>(X, Wa, bx_g + bofs, Xl, tid);
        __syncthreads();

        load_w64(Wf1_g + wofs, Wa, tid);
        load_w64(Wf2_g + wofs, Wb, tid);
        __syncthreads();

        // 32 tiles: 2 atoms (i0, i0+1) per tile, 128 padded pair-rows
        for (int tt = 0; tt < 32; tt++) {
            const int i0 = 2 * tt;

            // fill rbf tile: rr<64 -> atom i0, rr>=64 -> atom i0+1 (row m=63 pad)
            {
                int rr    = tid >> 1;
                int cpart = (tid & 1) * 32;
                int aSel  = rr >> 6;
                int m     = rr & 63;
                float* row = tA + rr * NPAD + cpart;
                if (m < 63) {
                    float dd = d[(i0 + aSel) * 64 + m];
#pragma unroll
                    for (int c = 0; c < 32; c++) {
                        float u = dd - cen[cpart + c];
                        row[c]  = __expf(-10.0f * u * u);
                    }
                } else {
#pragma unroll
                    for (int c = 0; c < 32; c++) row[c] = 0.0f;
                }
            }
            __syncthreads();

            gemm_nn<8, 1>(tA, Wa, bf1_g + bofs, tB, tid);  // h1 = tanh(rbf@Wf1+b)
            __syncthreads();
            gemm_nn<8, 1>(tB, Wb, bf2_g + bofs, tA, tid);  // h2 = tanh(h1@Wf2+b)
            __syncthreads();

            // cfconv: vs[i][c] = sum_m h2[m][c] * Xl[j(i,m)][c]
            {
                int t7   = tid & 127;
                int aSel = t7 >> 6;
                int c    = t7 & 63;
                int half = tid >> 7;
                int i    = i0 + aSel;
                int m0   = half * 32;
                int m1   = half ? 63 : 32;
                float s = 0.0f;
                for (int m = m0; m < m1; m++) {
                    int j = m + (m >= i);
                    s = fmaf(tA[(aSel * 64 + m) * NPAD + c], Xl[j * NPAD + c], s);
                }
                red[tid] = s;
            }
            __syncthreads();
            if (tid < 128) {
                int aSel = tid >> 6, c = tid & 63;
                vs[(i0 + aSel) * NPAD + c] = red[tid] + red[tid + 128];
            }
            __syncthreads();
        }

        // v = tanh(vs@Wv1+b); X += v@Wv2+b
        load_w64(Wv1_g + wofs, Wa, tid);
        load_w64(Wv2_g + wofs, Wb, tid);
        __syncthreads();
        gemm_nn<4, 1>(vs, Wa, bv1_g + bofs, tB, tid);
        __syncthreads();
        gemm_nn<4, 2>(tB, Wb, bv2_g + bofs, X, tid);
        __syncthreads();
    }

    // ---- output head: sum_a ( tanh(X@W1+b1) @ W2 + b2 ) ----
    {
        // W1 (64x32) into Wa; W2(32), b1(32), b2 into Wb
        const float4* src = reinterpret_cast<const float4*>(W1_g);
        float4*       dst = reinterpret_cast<float4*>(Wa);
        dst[tid] = src[tid];
        dst[tid + 256] = src[tid + 256];
        if (tid < 32) {
            Wb[tid]      = __ldg(W2_g + tid);
            Wb[64 + tid] = __ldg(b1_g + tid);
        }
        if (tid == 0) Wb[96] = __ldg(b2_g);
        __syncthreads();

        int a  = tid >> 2;           // atom 0..63
        int c0 = (tid & 3) * 8;      // 8 hidden cols
        float acc[8];
#pragma unroll
        for (int j = 0; j < 8; j++) acc[j] = Wb[64 + c0 + j];
#pragma unroll 4
        for (int k = 0; k < 64; k++) {
            float xa = X[a * NPAD + k];
#pragma unroll
            for (int j = 0; j < 8; j++)
                acc[j] = fmaf(xa, Wa[k * 32 + c0 + j], acc[j]);
        }
        float s = 0.0f;
#pragma unroll
        for (int j = 0; j < 8; j++) s = fmaf(fast_tanh(acc[j]), Wb[c0 + j], s);

        // block reduction
#pragma unroll
        for (int off = 16; off > 0; off >>= 1)
            s += __shfl_down_sync(0xffffffffu, s, off);
        if ((tid & 31) == 0) red[tid >> 5] = s;
        __syncthreads();
        if (tid == 0) {
            float tot = 0.0f;
#pragma unroll
            for (int w = 0; w < 8; w++) tot += red[w];
            out_g[b] = tot + 64.0f * Wb[96];
        }
    }
}

extern "C" void kernel_launch(void* const* d_in, const int* in_sizes, int n_in,
                              void* d_out, int out_size) {
    const float* r_g   = (const float*)d_in[0];
    const float* v1_g  = (const float*)d_in[1];
    const float* v2_g  = (const float*)d_in[2];
    const float* cen_g = (const float*)d_in[3];
    const float* Wx_g  = (const float*)d_in[4];
    const float* bx_g  = (const float*)d_in[5];
    const float* Wf1_g = (const float*)d_in[6];
    const float* bf1_g = (const float*)d_in[7];
    const float* Wf2_g = (const float*)d_in[8];
    const float* bf2_g = (const float*)d_in[9];
    const float* Wv1_g = (const float*)d_in[10];
    const float* bv1_g = (const float*)d_in[11];
    const float* Wv2_g = (const float*)d_in[12];
    const float* bv2_g = (const float*)d_in[13];
    const float* W1_g  = (const float*)d_in[14];
    const float* b1_g  = (const float*)d_in[15];
    const float* W2_g  = (const float*)d_in[16];
    const float* b2_g  = (const float*)d_in[17];
    float* out = (float*)d_out;

    int batch = in_sizes[0] / 192;

    cudaFuncSetAttribute(schnet_kernel,
                         cudaFuncAttributeMaxDynamicSharedMemorySize,
                         SMEM_BYTES);

    schnet_kernel<<<batch, 256, SMEM_BYTES>>>(
        r_g, v1_g, v2_g, cen_g, Wx_g, bx_g, Wf1_g, bf1_g, Wf2_g, bf2_g,
        Wv1_g, bv1_g, Wv2_g, bv2_g, W1_g, b1_g, W2_g, b2_g, out);
}

// round 2
// speedup vs baseline: 1.1015x; 1.1015x over previous
#include <cuda_runtime.h>

// ---------------------------------------------------------------------------
// SchNet fused kernel, round 2: FFMA2 (f32x2) gemms, 512 threads, 4-atom tiles.
//   1 CTA per batch element; everything SMEM-resident.
// ---------------------------------------------------------------------------

#define LDT 68   // padded row stride: even (8B a-loads), mult-of-4 (16B rows)

// shared memory layout (float offsets)
#define OFF_POS 0                        // 192
#define OFF_X   192                      // 64*LDT
#define OFF_XL  (OFF_X + 64*LDT)         // 64*64 (ld 64)
#define OFF_VS  (OFF_XL + 4096)          // 64*LDT
#define OFF_WA  (OFF_VS + 64*LDT)        // 4096 packed weights A
#define OFF_WB  (OFF_WA + 4096)          // 4096 packed weights B
#define OFF_TA  (OFF_WB + 4096)          // 256*LDT
#define OFF_TB  (OFF_TA + 256*LDT)       // 256*LDT (also reduction scratch)
#define SMEM_FLOATS (OFF_TB + 256*LDT)   // 56000
#define SMEM_BYTES  (SMEM_FLOATS * 4)    // 224000 bytes

typedef unsigned long long u64;

__device__ __forceinline__ float fast_tanh(float x) {
    float e = __expf(2.0f * x);
    return 1.0f - __fdividef(2.0f, e + 1.0f);
}

__device__ __forceinline__ void ffma2(u64& d, u64 a, u64 b) {
    asm("fma.rn.f32x2 %0, %1, %2, %0;" : "+l"(d) : "l"(a), "l"(b));
}

__device__ __forceinline__ void unpack2(u64 v, float& lo, float& hi) {
    asm("mov.b64 {%0, %1}, %2;" : "=f"(lo), "=f"(hi) : "l"(v));
}

// ---------------------------------------------------------------------------
// Weight packer: global row-major W[k][c] (64x64) -> SMEM pair-interleaved,
// bank-rotated layout. Unit (k2, p) holds {W[2k2][2p], W[2k2+1][2p],
// W[2k2][2p+1], W[2k2+1][2p+1]} (16B), placed at float offset
//   k2*128 + pos(p)*4,  pos(p) = (p & ~3) | (((p&3) + ((p>>3)&3)) & 3)
// so a warp's 8 column-groups hit 8 distinct 16B bank slots per load.
// ---------------------------------------------------------------------------
__device__ __forceinline__ void pack_w(const float* __restrict__ g,
                                       float* __restrict__ s, int tid) {
#pragma unroll
    for (int ii = 0; ii < 8; ii++) {
        int idx = tid + ii * 512;
        int k = idx >> 6, c = idx & 63;
        int p = c >> 1, cl = c & 1;
        int pos = (p & ~3) | (((p & 3) + ((p >> 3) & 3)) & 3);
        s[(k >> 1) * 128 + pos * 4 + cl * 2 + (k & 1)] = __ldg(g + idx);
    }
}

// ---------------------------------------------------------------------------
// C[ROWS x 64] = epi(A[ROWS x 64, ld lda] @ W(packed) + bias)
// EPI: 0 none, 1 tanh, 2 add-into-C.  Thread: R=ROWS/64 rows x 8 cols.
// f32x2 lanes accumulate even/odd-k partial sums; summed in epilogue.
// ---------------------------------------------------------------------------
template <int ROWS, int EPI>
__device__ __forceinline__ void gemm2(const float* __restrict__ A, int lda,
                                      const float* __restrict__ Wp,
                                      const float* __restrict__ bias,
                                      float* __restrict__ C, int ldc, int tid) {
    constexpr int R = ROWS / 64;
    const int rg = tid >> 3;       // 0..63
    const int cg = tid & 7;
    const int c0 = cg << 3;
    const int x  = (cg >> 1) & 3;

    const int u0 = (4 * cg + ((0 + x) & 3)) << 2;   // float offsets of units
    const int u1 = (4 * cg + ((1 + x) & 3)) << 2;
    const int u2 = (4 * cg + ((2 + x) & 3)) << 2;
    const int u3 = (4 * cg + ((3 + x) & 3)) << 2;

    const float* arow[R];
#pragma unroll
    for (int r = 0; r < R; r++) arow[r] = A + (rg + 64 * r) * lda;

    u64 acc[R][8];
#pragma unroll
    for (int r = 0; r < R; r++)
#pragma unroll
        for (int c = 0; c < 8; c++) acc[r][c] = 0ULL;

    const float* wk = Wp;
#pragma unroll 8
    for (int k2 = 0; k2 < 32; k2++) {
        ulonglong2 v0 = *(const ulonglong2*)(wk + u0);
        ulonglong2 v1 = *(const ulonglong2*)(wk + u1);
        ulonglong2 v2 = *(const ulonglong2*)(wk + u2);
        ulonglong2 v3 = *(const ulonglong2*)(wk + u3);
        u64 av[R];
#pragma unroll
        for (int r = 0; r < R; r++)
            av[r] = *(const u64*)(arow[r] + 2 * k2);
#pragma unroll
        for (int r = 0; r < R; r++) {
            ffma2(acc[r][0], av[r], v0.x); ffma2(acc[r][1], av[r], v0.y);
            ffma2(acc[r][2], av[r], v1.x); ffma2(acc[r][3], av[r], v1.y);
            ffma2(acc[r][4], av[r], v2.x); ffma2(acc[r][5], av[r], v2.y);
            ffma2(acc[r][6], av[r], v3.x); ffma2(acc[r][7], av[r], v3.y);
        }
        wk += 128;
    }

    const float4* bp = (const float4*)(bias + c0);
    float4 bA = __ldg(bp), bB = __ldg(bp + 1);
    float b8[8] = {bA.x, bA.y, bA.z, bA.w, bB.x, bB.y, bB.z, bB.w};

#pragma unroll
    for (int r = 0; r < R; r++) {
        float* cp = C + (rg + 64 * r) * ldc + c0;
        float o[8];
#pragma unroll
        for (int c = 0; c < 8; c++) {
            float lo, hi;
            unpack2(acc[r][c], lo, hi);
            float v = lo + hi + b8[c];
            if (EPI == 1) v = fast_tanh(v);
            o[c] = v;
        }
        if (EPI == 2) {
            float4 e0 = *(float4*)cp, e1 = *(float4*)(cp + 4);
            o[0] += e0.x; o[1] += e0.y; o[2] += e0.z; o[3] += e0.w;
            o[4] += e1.x; o[5] += e1.y; o[6] += e1.z; o[7] += e1.w;
        }
        *(float4*)cp       = make_float4(o[0], o[1], o[2], o[3]);
        *(float4*)(cp + 4) = make_float4(o[4], o[5], o[6], o[7]);
    }
}

__global__ void __launch_bounds__(512, 1)
schnet_kernel(const float* __restrict__ r_g,
              const float* __restrict__ v1_g,
              const float* __restrict__ v2_g,
              const float* __restrict__ cen_g,
              const float* __restrict__ Wx_g,  const float* __restrict__ bx_g,
              const float* __restrict__ Wf1_g, const float* __restrict__ bf1_g,
              const float* __restrict__ Wf2_g, const float* __restrict__ bf2_g,
              const float* __restrict__ Wv1_g, const float* __restrict__ bv1_g,
              const float* __restrict__ Wv2_g, const float* __restrict__ bv2_g,
              const float* __restrict__ W1_g,  const float* __restrict__ b1_g,
              const float* __restrict__ W2_g,  const float* __restrict__ b2_g,
              float* __restrict__ out_g) {
    extern __shared__ float sm[];
    float* pos = sm + OFF_POS;
    float* X   = sm + OFF_X;
    float* Xl  = sm + OFF_XL;
    float* vs  = sm + OFF_VS;
    float* Wa  = sm + OFF_WA;
    float* Wb  = sm + OFF_WB;
    float* tA  = sm + OFF_TA;
    float* tB  = sm + OFF_TB;   // doubles as reduction scratch

    const int tid = threadIdx.x;
    const int b   = blockIdx.x;

    // ---- init ----
    if (tid < 192) pos[tid] = r_g[b * 192 + tid];
#pragma unroll
    for (int ii = 0; ii < 8; ii++) {
        int idx = tid + ii * 512;
        int a = idx >> 6, f = idx & 63;
        X[a * LDT + f] = (a < 2) ? __ldg(v1_g + f) : __ldg(v2_g + f);
    }
    __syncthreads();

    // ---- 3 interaction blocks ----
    for (int t = 0; t < 3; t++) {
        const int wofs = t * 4096, bofs = t * 64;

        pack_w(Wx_g + wofs, Wa, tid);
        __syncthreads();
        gemm2<64, 0>(X, LDT, Wa, bx_g + bofs, Xl, 64, tid);
        __syncthreads();

        pack_w(Wf1_g + wofs, Wa, tid);
        pack_w(Wf2_g + wofs, Wb, tid);
        __syncthreads();

        // 16 tiles: 4 atoms per tile, 256 padded pair-rows
        for (int tt = 0; tt < 16; tt++) {
            const int i0 = 4 * tt;

            // rbf fill: row rr = aSel*64 + m (m=63 is zero padding)
            {
                int rr    = tid >> 1;
                int cpart = (tid & 1) * 32;
                int aSel  = rr >> 6;
                int m     = rr & 63;
                int i     = i0 + aSel;
                float* row = tA + rr * LDT + cpart;
                if (m < 63) {
                    int j = m + (m >= i);
                    float dx = pos[3 * i + 0] - pos[3 * j + 0];
                    float dy = pos[3 * i + 1] - pos[3 * j + 1];
                    float dz = pos[3 * i + 2] - pos[3 * j + 2];
                    float dd = sqrtf(fmaf(dx, dx, fmaf(dy, dy, dz * dz)));
#pragma unroll
                    for (int q = 0; q < 8; q++) {
                        float4 v;
                        float u0 = dd - (float)(cpart + 4 * q + 0) * 0.15625f;
                        float u1 = dd - (float)(cpart + 4 * q + 1) * 0.15625f;
                        float u2 = dd - (float)(cpart + 4 * q + 2) * 0.15625f;
                        float u3 = dd - (float)(cpart + 4 * q + 3) * 0.15625f;
                        v.x = __expf(-10.0f * u0 * u0);
                        v.y = __expf(-10.0f * u1 * u1);
                        v.z = __expf(-10.0f * u2 * u2);
                        v.w = __expf(-10.0f * u3 * u3);
                        *(float4*)(row + 4 * q) = v;
                    }
                } else {
                    float4 z = make_float4(0.f, 0.f, 0.f, 0.f);
#pragma unroll
                    for (int q = 0; q < 8; q++) *(float4*)(row + 4 * q) = z;
                }
            }
            __syncthreads();

            gemm2<256, 1>(tA, LDT, Wa, bf1_g + bofs, tB, LDT, tid);  // h1
            __syncthreads();
            gemm2<256, 1>(tB, LDT, Wb, bf2_g + bofs, tA, LDT, tid);  // h2
            __syncthreads();

            // cfconv: vs[i][c] = sum_m h2[a*64+m][c] * Xl[j(i,m)][c]
            {
                int a = tid >> 7;          // 0..3
                int c = (tid >> 1) & 63;
                int h = tid & 1;
                int i = i0 + a;
                int m0 = h * 32;
                int m1 = h ? 63 : 32;
                float s = 0.0f;
                for (int m = m0; m < m1; m++) {
                    int j = m + (m >= i);
                    s = fmaf(tA[(a * 64 + m) * LDT + c], Xl[j * 64 + c], s);
                }
                tB[tid] = s;   // red[a*128 + c*2 + h]
            }
            __syncthreads();
            if (tid < 256) {
                int a = tid >> 6, c = tid & 63;
                vs[(i0 + a) * LDT + c] =
                    tB[a * 128 + c * 2] + tB[a * 128 + c * 2 + 1];
            }
            __syncthreads();
        }

        pack_w(Wv1_g + wofs, Wa, tid);
        pack_w(Wv2_g + wofs, Wb, tid);
        __syncthreads();
        gemm2<64, 1>(vs, LDT, Wa, bv1_g + bofs, tB, LDT, tid);
        __syncthreads();
        gemm2<64, 2>(tB, LDT, Wb, bv2_g + bofs, X, LDT, tid);
        __syncthreads();
    }

    // ---- output head ----
    {
        // W1 (64x32) raw into Wa; W2(32) -> Wb[0..31], b1(32) -> Wb[32..63], b2 -> Wb[64]
#pragma unroll
        for (int ii = 0; ii < 4; ii++) Wa[tid + 512 * ii] = __ldg(W1_g + tid + 512 * ii);
        if (tid < 32) {
            Wb[tid]      = __ldg(W2_g + tid);
            Wb[32 + tid] = __ldg(b1_g + tid);
        }
        if (tid == 0) Wb[64] = __ldg(b2_g);
        __syncthreads();

        int a  = tid >> 3;          // atom 0..63
        int cq = (tid & 7) * 4;     // 4 hidden cols
        float acc0 = Wb[32 + cq + 0], acc1 = Wb[32 + cq + 1];
        float acc2 = Wb[32 + cq + 2], acc3 = Wb[32 + cq + 3];
#pragma unroll 8
        for (int k = 0; k < 64; k++) {
            float xa = X[a * LDT + k];
            const float* wr = Wa + k * 32 + cq;
            acc0 = fmaf(xa, wr[0], acc0);
            acc1 = fmaf(xa, wr[1], acc1);
            acc2 = fmaf(xa, wr[2], acc2);
            acc3 = fmaf(xa, wr[3], acc3);
        }
        float s = fast_tanh(acc0) * Wb[cq + 0] + fast_tanh(acc1) * Wb[cq + 1] +
                  fast_tanh(acc2) * Wb[cq + 2] + fast_tanh(acc3) * Wb[cq + 3];

#pragma unroll
        for (int off = 16; off > 0; off >>= 1)
            s += __shfl_xor_sync(0xffffffffu, s, off);
        if ((tid & 31) == 0) tA[tid >> 5] = s;
        __syncthreads();
        if (tid == 0) {
            float tot = 0.0f;
#pragma unroll
            for (int w = 0; w < 16; w++) tot += tA[w];
            out_g[b] = tot + 64.0f * Wb[64];
        }
    }
}

extern "C" void kernel_launch(void* const* d_in, const int* in_sizes, int n_in,
                              void* d_out, int out_size) {
    const float* r_g   = (const float*)d_in[0];
    const float* v1_g  = (const float*)d_in[1];
    const float* v2_g  = (const float*)d_in[2];
    const float* cen_g = (const float*)d_in[3];
    const float* Wx_g  = (const float*)d_in[4];
    const float* bx_g  = (const float*)d_in[5];
    const float* Wf1_g = (const float*)d_in[6];
    const float* bf1_g = (const float*)d_in[7];
    const float* Wf2_g = (const float*)d_in[8];
    const float* bf2_g = (const float*)d_in[9];
    const float* Wv1_g = (const float*)d_in[10];
    const float* bv1_g = (const float*)d_in[11];
    const float* Wv2_g = (const float*)d_in[12];
    const float* bv2_g = (const float*)d_in[13];
    const float* W1_g  = (const float*)d_in[14];
    const float* b1_g  = (const float*)d_in[15];
    const float* W2_g  = (const float*)d_in[16];
    const float* b2_g  = (const float*)d_in[17];
    float* out = (float*)d_out;

    int batch = in_sizes[0] / 192;

    cudaFuncSetAttribute(schnet_kernel,
                         cudaFuncAttributeMaxDynamicSharedMemorySize,
                         SMEM_BYTES);

    schnet_kernel<<<batch, 512, SMEM_BYTES>>>(
        r_g, v1_g, v2_g, cen_g, Wx_g, bx_g, Wf1_g, bf1_g, Wf2_g, bf2_g,
        Wv1_g, bv1_g, Wv2_g, bv2_g, W1_g, b1_g, W2_g, b2_g, out);
}

// round 3
// speedup vs baseline: 1.1021x; 1.0005x over previous
#include <cuda_runtime.h>

// ---------------------------------------------------------------------------
// SchNet fused kernel, round 2: FFMA2 (f32x2) gemms, 512 threads, 4-atom tiles.
//   1 CTA per batch element; everything SMEM-resident.
// ---------------------------------------------------------------------------

#define LDT 68   // padded row stride: even (8B a-loads), mult-of-4 (16B rows)

// shared memory layout (float offsets)
#define OFF_POS 0                        // 192
#define OFF_X   192                      // 64*LDT
#define OFF_XL  (OFF_X + 64*LDT)         // 64*64 (ld 64)
#define OFF_VS  (OFF_XL + 4096)          // 64*LDT
#define OFF_WA  (OFF_VS + 64*LDT)        // 4096 packed weights A
#define OFF_WB  (OFF_WA + 4096)          // 4096 packed weights B
#define OFF_TA  (OFF_WB + 4096)          // 256*LDT
#define OFF_TB  (OFF_TA + 256*LDT)       // 256*LDT (also reduction scratch)
#define SMEM_FLOATS (OFF_TB + 256*LDT)   // 56000
#define SMEM_BYTES  (SMEM_FLOATS * 4)    // 224000 bytes

typedef unsigned long long u64;

__device__ __forceinline__ float fast_tanh(float x) {
    float e = __expf(2.0f * x);
    return 1.0f - __fdividef(2.0f, e + 1.0f);
}

__device__ __forceinline__ void ffma2(u64& d, u64 a, u64 b) {
    asm("fma.rn.f32x2 %0, %1, %2, %0;" : "+l"(d) : "l"(a), "l"(b));
}

__device__ __forceinline__ void unpack2(u64 v, float& lo, float& hi) {
    asm("mov.b64 {%0, %1}, %2;" : "=f"(lo), "=f"(hi) : "l"(v));
}

// ---------------------------------------------------------------------------
// Weight packer: global row-major W[k][c] (64x64) -> SMEM pair-interleaved,
// bank-rotated layout. Unit (k2, p) holds {W[2k2][2p], W[2k2+1][2p],
// W[2k2][2p+1], W[2k2+1][2p+1]} (16B), placed at float offset
//   k2*128 + pos(p)*4,  pos(p) = (p & ~3) | (((p&3) + ((p>>3)&3)) & 3)
// so a warp's 8 column-groups hit 8 distinct 16B bank slots per load.
// ---------------------------------------------------------------------------
__device__ __forceinline__ void pack_w(const float* __restrict__ g,
                                       float* __restrict__ s, int tid) {
#pragma unroll
    for (int ii = 0; ii < 8; ii++) {
        int idx = tid + ii * 512;
        int k = idx >> 6, c = idx & 63;
        int p = c >> 1, cl = c & 1;
        int pos = (p & ~3) | (((p & 3) + ((p >> 3) & 3)) & 3);
        s[(k >> 1) * 128 + pos * 4 + cl * 2 + (k & 1)] = __ldg(g + idx);
    }
}

// ---------------------------------------------------------------------------
// C[ROWS x 64] = epi(A[ROWS x 64, ld lda] @ W(packed) + bias)
// EPI: 0 none, 1 tanh, 2 add-into-C.  Thread: R=ROWS/64 rows x 8 cols.
// f32x2 lanes accumulate even/odd-k partial sums; summed in epilogue.
// ---------------------------------------------------------------------------
template <int ROWS, int EPI>
__device__ __forceinline__ void gemm2(const float* __restrict__ A, int lda,
                                      const float* __restrict__ Wp,
                                      const float* __restrict__ bias,
                                      float* __restrict__ C, int ldc, int tid) {
    constexpr int R = ROWS / 64;
    const int rg = tid >> 3;       // 0..63
    const int cg = tid & 7;
    const int c0 = cg << 3;
    const int x  = (cg >> 1) & 3;

    const int u0 = (4 * cg + ((0 + x) & 3)) << 2;   // float offsets of units
    const int u1 = (4 * cg + ((1 + x) & 3)) << 2;
    const int u2 = (4 * cg + ((2 + x) & 3)) << 2;
    const int u3 = (4 * cg + ((3 + x) & 3)) << 2;

    const float* arow[R];
#pragma unroll
    for (int r = 0; r < R; r++) arow[r] = A + (rg + 64 * r) * lda;

    u64 acc[R][8];
#pragma unroll
    for (int r = 0; r < R; r++)
#pragma unroll
        for (int c = 0; c < 8; c++) acc[r][c] = 0ULL;

    const float* wk = Wp;
#pragma unroll 8
    for (int k2 = 0; k2 < 32; k2++) {
        ulonglong2 v0 = *(const ulonglong2*)(wk + u0);
        ulonglong2 v1 = *(const ulonglong2*)(wk + u1);
        ulonglong2 v2 = *(const ulonglong2*)(wk + u2);
        ulonglong2 v3 = *(const ulonglong2*)(wk + u3);
        u64 av[R];
#pragma unroll
        for (int r = 0; r < R; r++)
            av[r] = *(const u64*)(arow[r] + 2 * k2);
#pragma unroll
        for (int r = 0; r < R; r++) {
            ffma2(acc[r][0], av[r], v0.x); ffma2(acc[r][1], av[r], v0.y);
            ffma2(acc[r][2], av[r], v1.x); ffma2(acc[r][3], av[r], v1.y);
            ffma2(acc[r][4], av[r], v2.x); ffma2(acc[r][5], av[r], v2.y);
            ffma2(acc[r][6], av[r], v3.x); ffma2(acc[r][7], av[r], v3.y);
        }
        wk += 128;
    }

    const float4* bp = (const float4*)(bias + c0);
    float4 bA = __ldg(bp), bB = __ldg(bp + 1);
    float b8[8] = {bA.x, bA.y, bA.z, bA.w, bB.x, bB.y, bB.z, bB.w};

#pragma unroll
    for (int r = 0; r < R; r++) {
        float* cp = C + (rg + 64 * r) * ldc + c0;
        float o[8];
#pragma unroll
        for (int c = 0; c < 8; c++) {
            float lo, hi;
            unpack2(acc[r][c], lo, hi);
            float v = lo + hi + b8[c];
            if (EPI == 1) v = fast_tanh(v);
            o[c] = v;
        }
        if (EPI == 2) {
            float4 e0 = *(float4*)cp, e1 = *(float4*)(cp + 4);
            o[0] += e0.x; o[1] += e0.y; o[2] += e0.z; o[3] += e0.w;
            o[4] += e1.x; o[5] += e1.y; o[6] += e1.z; o[7] += e1.w;
        }
        *(float4*)cp       = make_float4(o[0], o[1], o[2], o[3]);
        *(float4*)(cp + 4) = make_float4(o[4], o[5], o[6], o[7]);
    }
}

__global__ void __launch_bounds__(512, 1)
schnet_kernel(const float* __restrict__ r_g,
              const float* __restrict__ v1_g,
              const float* __restrict__ v2_g,
              const float* __restrict__ cen_g,
              const float* __restrict__ Wx_g,  const float* __restrict__ bx_g,
              const float* __restrict__ Wf1_g, const float* __restrict__ bf1_g,
              const float* __restrict__ Wf2_g, const float* __restrict__ bf2_g,
              const float* __restrict__ Wv1_g, const float* __restrict__ bv1_g,
              const float* __restrict__ Wv2_g, const float* __restrict__ bv2_g,
              const float* __restrict__ W1_g,  const float* __restrict__ b1_g,
              const float* __restrict__ W2_g,  const float* __restrict__ b2_g,
              float* __restrict__ out_g) {
    extern __shared__ float sm[];
    float* pos = sm + OFF_POS;
    float* X   = sm + OFF_X;
    float* Xl  = sm + OFF_XL;
    float* vs  = sm + OFF_VS;
    float* Wa  = sm + OFF_WA;
    float* Wb  = sm + OFF_WB;
    float* tA  = sm + OFF_TA;
    float* tB  = sm + OFF_TB;   // doubles as reduction scratch

    const int tid = threadIdx.x;
    const int b   = blockIdx.x;

    // ---- init ----
    if (tid < 192) pos[tid] = r_g[b * 192 + tid];
#pragma unroll
    for (int ii = 0; ii < 8; ii++) {
        int idx = tid + ii * 512;
        int a = idx >> 6, f = idx & 63;
        X[a * LDT + f] = (a < 2) ? __ldg(v1_g + f) : __ldg(v2_g + f);
    }
    __syncthreads();

    // ---- 3 interaction blocks ----
    for (int t = 0; t < 3; t++) {
        const int wofs = t * 4096, bofs = t * 64;

        pack_w(Wx_g + wofs, Wa, tid);
        __syncthreads();
        gemm2<64, 0>(X, LDT, Wa, bx_g + bofs, Xl, 64, tid);
        __syncthreads();

        pack_w(Wf1_g + wofs, Wa, tid);
        pack_w(Wf2_g + wofs, Wb, tid);
        __syncthreads();

        // 16 tiles: 4 atoms per tile, 256 padded pair-rows
        for (int tt = 0; tt < 16; tt++) {
            const int i0 = 4 * tt;

            // rbf fill: row rr = aSel*64 + m (m=63 is zero padding)
            {
                int rr    = tid >> 1;
                int cpart = (tid & 1) * 32;
                int aSel  = rr >> 6;
                int m     = rr & 63;
                int i     = i0 + aSel;
                float* row = tA + rr * LDT + cpart;
                if (m < 63) {
                    int j = m + (m >= i);
                    float dx = pos[3 * i + 0] - pos[3 * j + 0];
                    float dy = pos[3 * i + 1] - pos[3 * j + 1];
                    float dz = pos[3 * i + 2] - pos[3 * j + 2];
                    float dd = sqrtf(fmaf(dx, dx, fmaf(dy, dy, dz * dz)));
#pragma unroll
                    for (int q = 0; q < 8; q++) {
                        float4 v;
                        float u0 = dd - (float)(cpart + 4 * q + 0) * 0.15625f;
                        float u1 = dd - (float)(cpart + 4 * q + 1) * 0.15625f;
                        float u2 = dd - (float)(cpart + 4 * q + 2) * 0.15625f;
                        float u3 = dd - (float)(cpart + 4 * q + 3) * 0.15625f;
                        v.x = __expf(-10.0f * u0 * u0);
                        v.y = __expf(-10.0f * u1 * u1);
                        v.z = __expf(-10.0f * u2 * u2);
                        v.w = __expf(-10.0f * u3 * u3);
                        *(float4*)(row + 4 * q) = v;
                    }
                } else {
                    float4 z = make_float4(0.f, 0.f, 0.f, 0.f);
#pragma unroll
                    for (int q = 0; q < 8; q++) *(float4*)(row + 4 * q) = z;
                }
            }
            __syncthreads();

            gemm2<256, 1>(tA, LDT, Wa, bf1_g + bofs, tB, LDT, tid);  // h1
            __syncthreads();
            gemm2<256, 1>(tB, LDT, Wb, bf2_g + bofs, tA, LDT, tid);  // h2
            __syncthreads();

            // cfconv: vs[i][c] = sum_m h2[a*64+m][c] * Xl[j(i,m)][c]
            {
                int a = tid >> 7;          // 0..3
                int c = (tid >> 1) & 63;
                int h = tid & 1;
                int i = i0 + a;
                int m0 = h * 32;
                int m1 = h ? 63 : 32;
                float s = 0.0f;
                for (int m = m0; m < m1; m++) {
                    int j = m + (m >= i);
                    s = fmaf(tA[(a * 64 + m) * LDT + c], Xl[j * 64 + c], s);
                }
                tB[tid] = s;   // red[a*128 + c*2 + h]
            }
            __syncthreads();
            if (tid < 256) {
                int a = tid >> 6, c = tid & 63;
                vs[(i0 + a) * LDT + c] =
                    tB[a * 128 + c * 2] + tB[a * 128 + c * 2 + 1];
            }
            __syncthreads();
        }

        pack_w(Wv1_g + wofs, Wa, tid);
        pack_w(Wv2_g + wofs, Wb, tid);
        __syncthreads();
        gemm2<64, 1>(vs, LDT, Wa, bv1_g + bofs, tB, LDT, tid);
        __syncthreads();
        gemm2<64, 2>(tB, LDT, Wb, bv2_g + bofs, X, LDT, tid);
        __syncthreads();
    }

    // ---- output head ----
    {
        // W1 (64x32) raw into Wa; W2(32) -> Wb[0..31], b1(32) -> Wb[32..63], b2 -> Wb[64]
#pragma unroll
        for (int ii = 0; ii < 4; ii++) Wa[tid + 512 * ii] = __ldg(W1_g + tid + 512 * ii);
        if (tid < 32) {
            Wb[tid]      = __ldg(W2_g + tid);
            Wb[32 + tid] = __ldg(b1_g + tid);
        }
        if (tid == 0) Wb[64] = __ldg(b2_g);
        __syncthreads();

        int a  = tid >> 3;          // atom 0..63
        int cq = (tid & 7) * 4;     // 4 hidden cols
        float acc0 = Wb[32 + cq + 0], acc1 = Wb[32 + cq + 1];
        float acc2 = Wb[32 + cq + 2], acc3 = Wb[32 + cq + 3];
#pragma unroll 8
        for (int k = 0; k < 64; k++) {
            float xa = X[a * LDT + k];
            const float* wr = Wa + k * 32 + cq;
            acc0 = fmaf(xa, wr[0], acc0);
            acc1 = fmaf(xa, wr[1], acc1);
            acc2 = fmaf(xa, wr[2], acc2);
            acc3 = fmaf(xa, wr[3], acc3);
        }
        float s = fast_tanh(acc0) * Wb[cq + 0] + fast_tanh(acc1) * Wb[cq + 1] +
                  fast_tanh(acc2) * Wb[cq + 2] + fast_tanh(acc3) * Wb[cq + 3];

#pragma unroll
        for (int off = 16; off > 0; off >>= 1)
            s += __shfl_xor_sync(0xffffffffu, s, off);
        if ((tid & 31) == 0) tA[tid >> 5] = s;
        __syncthreads();
        if (tid == 0) {
            float tot = 0.0f;
#pragma unroll
            for (int w = 0; w < 16; w++) tot += tA[w];
            out_g[b] = tot + 64.0f * Wb[64];
        }
    }
}

extern "C" void kernel_launch(void* const* d_in, const int* in_sizes, int n_in,
                              void* d_out, int out_size) {
    const float* r_g   = (const float*)d_in[0];
    const float* v1_g  = (const float*)d_in[1];
    const float* v2_g  = (const float*)d_in[2];
    const float* cen_g = (const float*)d_in[3];
    const float* Wx_g  = (const float*)d_in[4];
    const float* bx_g  = (const float*)d_in[5];
    const float* Wf1_g = (const float*)d_in[6];
    const float* bf1_g = (const float*)d_in[7];
    const float* Wf2_g = (const float*)d_in[8];
    const float* bf2_g = (const float*)d_in[9];
    const float* Wv1_g = (const float*)d_in[10];
    const float* bv1_g = (const float*)d_in[11];
    const float* Wv2_g = (const float*)d_in[12];
    const float* bv2_g = (const float*)d_in[13];
    const float* W1_g  = (const float*)d_in[14];
    const float* b1_g  = (const float*)d_in[15];
    const float* W2_g  = (const float*)d_in[16];
    const float* b2_g  = (const float*)d_in[17];
    float* out = (float*)d_out;

    int batch = in_sizes[0] / 192;

    cudaFuncSetAttribute(schnet_kernel,
                         cudaFuncAttributeMaxDynamicSharedMemorySize,
                         SMEM_BYTES);

    schnet_kernel<<<batch, 512, SMEM_BYTES>>>(
        r_g, v1_g, v2_g, cen_g, Wx_g, bx_g, Wf1_g, bf1_g, Wf2_g, bf2_g,
        Wv1_g, bv1_g, Wv2_g, bv2_g, W1_g, b1_g, W2_g, b2_g, out);
}

// round 5
// speedup vs baseline: 2.4873x; 2.2569x over previous
#include <cuda_runtime.h>
#include <cstdint>

// ---------------------------------------------------------------------------
// SchNet fused kernel, round 5: legacy mma.sync (HMMA tf32) filter GEMMs.
// No tcgen05 (harness targets sm_103 w/o 'a'). 1 CTA/batch, 512 threads.
// Filter GEMMs: 16 warps as 4 row-blocks(atoms) x 4 col-blocks over
// 256-row tiles, m16n8k8 tf32 MMA with k-mod-4 interleaved SMEM layout
// (all fragment loads are conflict-free LDS.128).
// ---------------------------------------------------------------------------

typedef unsigned long long u64;
typedef unsigned int u32;

#define LDA 72   // A-tile / Wt row stride (floats)
#define LDX 68   // X / vs / tmpV stride (scalar path)

// float offsets
#define OFF_POS   0        // 192 (pad 256)
#define OFF_BIAS  256      // 128: bf1[64], bf2[64]
#define OFF_XL    384      // 64*72 = 4608
#define OFF_X     4992     // 64*68 = 4352
#define OFF_VS    9344     // 4352
#define OFF_WT1   13696    // 64*72 = 4608
#define OFF_WT2   18304    // 4608
#define OFF_A     22912    // 256*72 = 18432
#define SMEM_FLOATS 41344
#define SMEM_BYTES  (SMEM_FLOATS * 4)   // 165376

__device__ __forceinline__ float fast_tanh(float x) {
    float e = __expf(2.0f * x);
    return 1.0f - __fdividef(2.0f, e + 1.0f);
}
__device__ __forceinline__ float tf32r(float f) {
    u32 v; asm("cvt.rna.tf32.f32 %0, %1;" : "=r"(v) : "f"(f));
    return __uint_as_float(v);
}
// k-mod-4 interleaved column offset: offs = {0,16,36,52}[k&3]
__device__ __forceinline__ int koffs(int km4) {
    return (km4 & 1) * 16 + (km4 & 2) * 18;
}

// ---------------------------------------------------------------------------
// Warp MMA block: D[4][2][4] = A(64 rows x 64k, perm, stride 72) @ Wt(16 cols)
// A rows [row0, row0+64); Wt cols via Wtp already offset to this warp's block.
// ---------------------------------------------------------------------------
__device__ __forceinline__ void mma_block(const float* __restrict__ Ap, int row0,
                                          const float* __restrict__ Wtp,
                                          float (&D)[4][2][4], int g, int tig) {
    const int offt = koffs(tig);
    float Bf[2][16];
#pragma unroll
    for (int nb = 0; nb < 2; nb++) {
        const float* bp = Wtp + (nb * 8 + g) * LDA + offt;
#pragma unroll
        for (int q = 0; q < 4; q++)
            *(float4*)&Bf[nb][4 * q] = *(const float4*)(bp + 4 * q);
    }
#pragma unroll
    for (int mg = 0; mg < 4; mg++) {
#pragma unroll
        for (int nb = 0; nb < 2; nb++)
#pragma unroll
            for (int i = 0; i < 4; i++) D[mg][nb][i] = 0.0f;
        float Aa[16], Ab[16];
        const float* ap = Ap + (row0 + mg * 16 + g) * LDA + offt;
#pragma unroll
        for (int q = 0; q < 4; q++) {
            *(float4*)&Aa[4 * q] = *(const float4*)(ap + 4 * q);
            *(float4*)&Ab[4 * q] = *(const float4*)(ap + 8 * LDA + 4 * q);
        }
#pragma unroll
        for (int s = 0; s < 8; s++) {
            u32 a0 = __float_as_uint(Aa[2 * s]);
            u32 a2 = __float_as_uint(Aa[2 * s + 1]);
            u32 a1 = __float_as_uint(Ab[2 * s]);
            u32 a3 = __float_as_uint(Ab[2 * s + 1]);
#pragma unroll
            for (int nb = 0; nb < 2; nb++) {
                u32 b0 = __float_as_uint(Bf[nb][2 * s]);
                u32 b1 = __float_as_uint(Bf[nb][2 * s + 1]);
                asm("mma.sync.aligned.m16n8k8.row.col.f32.tf32.tf32.f32 "
                    "{%0,%1,%2,%3}, {%4,%5,%6,%7}, {%8,%9}, {%0,%1,%2,%3};"
                    : "+f"(D[mg][nb][0]), "+f"(D[mg][nb][1]),
                      "+f"(D[mg][nb][2]), "+f"(D[mg][nb][3])
                    : "r"(a0), "r"(a1), "r"(a2), "r"(a3), "r"(b0), "r"(b1));
            }
        }
    }
}

// W[k][n] (64x64 row-major, global) -> Wt_perm[n][pos(k)] tf32, stride 72
__device__ __forceinline__ void store_wT(const float* __restrict__ g,
                                         float* __restrict__ s, int tid) {
#pragma unroll
    for (int ii = 0; ii < 8; ii++) {
        int idx = tid + ii * 512;
        int k = idx >> 6, n = idx & 63;
        s[n * LDA + koffs(k & 3) + (k >> 2)] = tf32r(__ldg(g + idx));
    }
}

// ---- scalar FFMA2 machinery for small 64x64 GEMMs (proven round-2 path) ----
__device__ __forceinline__ void ffma2(u64& d, u64 a, u64 b) {
    asm("fma.rn.f32x2 %0, %1, %2, %0;" : "+l"(d) : "l"(a), "l"(b));
}
__device__ __forceinline__ void unpack2(u64 v, float& lo, float& hi) {
    asm("mov.b64 {%0, %1}, %2;" : "=f"(lo), "=f"(hi) : "l"(v));
}
__device__ __forceinline__ void pack_w(const float* __restrict__ g,
                                       float* __restrict__ s, int tid) {
#pragma unroll
    for (int ii = 0; ii < 8; ii++) {
        int idx = tid + ii * 512;
        int k = idx >> 6, c = idx & 63;
        int p = c >> 1, cl = c & 1;
        int pos = (p & ~3) | (((p & 3) + ((p >> 3) & 3)) & 3);
        s[(k >> 1) * 128 + pos * 4 + cl * 2 + (k & 1)] = __ldg(g + idx);
    }
}
template <int EPI>
__device__ __forceinline__ void gemm2(const float* __restrict__ A, int lda,
                                      const float* __restrict__ Wp,
                                      const float* __restrict__ bias,
                                      float* __restrict__ C, int ldc, int tid) {
    const int rg = tid >> 3, cg = tid & 7, c0 = cg << 3, x = (cg >> 1) & 3;
    const int u0 = (4 * cg + ((0 + x) & 3)) << 2;
    const int u1 = (4 * cg + ((1 + x) & 3)) << 2;
    const int u2 = (4 * cg + ((2 + x) & 3)) << 2;
    const int u3 = (4 * cg + ((3 + x) & 3)) << 2;
    const float* arow = A + rg * lda;
    u64 acc[8];
#pragma unroll
    for (int c = 0; c < 8; c++) acc[c] = 0ULL;
    const float* wk = Wp;
#pragma unroll 8
    for (int k2 = 0; k2 < 32; k2++) {
        ulonglong2 v0 = *(const ulonglong2*)(wk + u0);
        ulonglong2 v1 = *(const ulonglong2*)(wk + u1);
        ulonglong2 v2 = *(const ulonglong2*)(wk + u2);
        ulonglong2 v3 = *(const ulonglong2*)(wk + u3);
        u64 av = *(const u64*)(arow + 2 * k2);
        ffma2(acc[0], av, v0.x); ffma2(acc[1], av, v0.y);
        ffma2(acc[2], av, v1.x); ffma2(acc[3], av, v1.y);
        ffma2(acc[4], av, v2.x); ffma2(acc[5], av, v2.y);
        ffma2(acc[6], av, v3.x); ffma2(acc[7], av, v3.y);
        wk += 128;
    }
    const float4* bp = (const float4*)(bias + c0);
    float4 bA = __ldg(bp), bB = __ldg(bp + 1);
    float b8[8] = {bA.x, bA.y, bA.z, bA.w, bB.x, bB.y, bB.z, bB.w};
    float* cp = C + rg * ldc + c0;
    float o[8];
#pragma unroll
    for (int c = 0; c < 8; c++) {
        float lo, hi; unpack2(acc[c], lo, hi);
        float v = lo + hi + b8[c];
        if (EPI == 1) v = fast_tanh(v);
        o[c] = v;
    }
    if (EPI == 2) {
        float4 e0 = *(float4*)cp, e1 = *(float4*)(cp + 4);
        o[0] += e0.x; o[1] += e0.y; o[2] += e0.z; o[3] += e0.w;
        o[4] += e1.x; o[5] += e1.y; o[6] += e1.z; o[7] += e1.w;
    }
    *(float4*)cp       = make_float4(o[0], o[1], o[2], o[3]);
    *(float4*)(cp + 4) = make_float4(o[4], o[5], o[6], o[7]);
}

__global__ void __launch_bounds__(512, 1)
schnet_kernel(const float* __restrict__ r_g, const float* __restrict__ v1_g,
              const float* __restrict__ v2_g, const float* __restrict__ cen_g,
              const float* __restrict__ Wx_g,  const float* __restrict__ bx_g,
              const float* __restrict__ Wf1_g, const float* __restrict__ bf1_g,
              const float* __restrict__ Wf2_g, const float* __restrict__ bf2_g,
              const float* __restrict__ Wv1_g, const float* __restrict__ bv1_g,
              const float* __restrict__ Wv2_g, const float* __restrict__ bv2_g,
              const float* __restrict__ W1_g,  const float* __restrict__ b1_g,
              const float* __restrict__ W2_g,  const float* __restrict__ b2_g,
              float* __restrict__ out_g) {
    extern __shared__ float sm[];
    float* pos    = sm + OFF_POS;
    float* bias_s = sm + OFF_BIAS;
    float* Xl     = sm + OFF_XL;
    float* X      = sm + OFF_X;
    float* vs     = sm + OFF_VS;
    float* Wt1    = sm + OFF_WT1;
    float* Wt2    = sm + OFF_WT2;
    float* Ap     = sm + OFF_A;
    float* WPA    = sm + OFF_A;          // scalar scratch (A region reuse)
    float* WPB    = sm + OFF_A + 4096;
    float* tmpV   = sm + OFF_A + 8192;

    const int tid  = threadIdx.x, b = blockIdx.x;
    const int wid  = tid >> 5, lane = tid & 31;
    const int rb   = wid >> 2, cb = wid & 3;     // row-block(atom), col-block
    const int g    = lane >> 2, tig = lane & 3;

    // ---- init ----
    if (tid < 192) pos[tid] = r_g[b * 192 + tid];
#pragma unroll
    for (int ii = 0; ii < 8; ii++) {
        int idx = tid + ii * 512;
        int a = idx >> 6, f = idx & 63;
        X[a * LDX + f] = (a < 2) ? __ldg(v1_g + f) : __ldg(v2_g + f);
    }
    __syncthreads();

    float D[4][2][4];

    for (int t = 0; t < 3; t++) {
        const int wofs = t * 4096, bofs = t * 64;

        // stage weights: Wx (scalar packed), Wf1/Wf2 (tf32 perm), biases
        pack_w(Wx_g + wofs, WPA, tid);
        store_wT(Wf1_g + wofs, Wt1, tid);
        store_wT(Wf2_g + wofs, Wt2, tid);
        if (tid < 64) {
            bias_s[tid]      = __ldg(bf1_g + bofs + tid);
            bias_s[64 + tid] = __ldg(bf2_g + bofs + tid);
        }
        __syncthreads();
        gemm2<0>(X, LDX, WPA, bx_g + bofs, Xl, LDA, tid);  // Xl = X@Wx+bx
        __syncthreads();

        const float* Wt1w = Wt1 + cb * 16 * LDA;
        const float* Wt2w = Wt2 + cb * 16 * LDA;

        // ---- 16 tiles of 4 atoms (256 pair rows) ----
        for (int tt = 0; tt < 16; tt++) {
            const int i0 = 4 * tt;

            // rbf fill into A perm layout; row rr = aSel*64 + m (m=63 pad)
            {
                int rr = tid >> 1, half = tid & 1;
                int aSel = rr >> 6, m = rr & 63;
                int i = i0 + aSel;
                float* arow = Ap + rr * LDA;
                if (m < 63) {
                    int j = m + (m >= i);
                    float dx = pos[3 * i + 0] - pos[3 * j + 0];
                    float dy = pos[3 * i + 1] - pos[3 * j + 1];
                    float dz = pos[3 * i + 2] - pos[3 * j + 2];
                    float dd = sqrtf(fmaf(dx, dx, fmaf(dy, dy, dz * dz)));
#pragma unroll
                    for (int h = 0; h < 2; h++) {
                        int km4 = 2 * half + h;
                        float* grp = arow + koffs(km4);
                        float cbase = dd - (float)km4 * 0.15625f;
#pragma unroll
                        for (int q = 0; q < 4; q++) {
                            float u0 = cbase - (float)(4 * q + 0) * 0.625f;
                            float u1 = cbase - (float)(4 * q + 1) * 0.625f;
                            float u2 = cbase - (float)(4 * q + 2) * 0.625f;
                            float u3 = cbase - (float)(4 * q + 3) * 0.625f;
                            float4 v;
                            v.x = tf32r(__expf(-10.0f * u0 * u0));
                            v.y = tf32r(__expf(-10.0f * u1 * u1));
                            v.z = tf32r(__expf(-10.0f * u2 * u2));
                            v.w = tf32r(__expf(-10.0f * u3 * u3));
                            *(float4*)(grp + 4 * q) = v;
                        }
                    }
                } else {
                    float4 z = make_float4(0.f, 0.f, 0.f, 0.f);
#pragma unroll
                    for (int h = 0; h < 2; h++) {
                        float* grp = arow + koffs(2 * half + h);
#pragma unroll
                        for (int q = 0; q < 4; q++) *(float4*)(grp + 4 * q) = z;
                    }
                }
            }
            __syncthreads();

            // GEMM1: D = rbf @ Wf1^T
            mma_block(Ap, rb * 64, Wt1w, D, g, tig);
            __syncthreads();   // all A reads done

            // epilogue1: h1 = tanh(D + bf1) -> A (perm, tf32)
            {
                const int idxb = cb * 4 + (tig >> 1);
                const int p0 = (tig & 1) * 36;
#pragma unroll
                for (int nb = 0; nb < 2; nb++) {
                    float2 bb = *(float2*)&bias_s[cb * 16 + nb * 8 + 2 * tig];
                    int pa = p0 + idxb + 2 * nb;
#pragma unroll
                    for (int mg = 0; mg < 4; mg++) {
                        float* r0p = Ap + (rb * 64 + mg * 16 + g) * LDA;
                        float* r1p = r0p + 8 * LDA;
                        r0p[pa]      = tf32r(fast_tanh(D[mg][nb][0] + bb.x));
                        r0p[pa + 16] = tf32r(fast_tanh(D[mg][nb][1] + bb.y));
                        r1p[pa]      = tf32r(fast_tanh(D[mg][nb][2] + bb.x));
                        r1p[pa + 16] = tf32r(fast_tanh(D[mg][nb][3] + bb.y));
                    }
                }
            }
            __syncthreads();

            // GEMM2: D = h1 @ Wf2^T
            mma_block(Ap, rb * 64, Wt2w, D, g, tig);

            // epilogue2: h2 = tanh(D + bf2); cfconv vs[i][c] = sum_m h2*Xl[j]
            {
                const int i_atom = i0 + rb;
                float2 bb0 = *(float2*)&bias_s[64 + cb * 16 + 2 * tig];
                float2 bb1 = *(float2*)&bias_s[64 + cb * 16 + 8 + 2 * tig];
                float a00 = 0.f, a01 = 0.f, a10 = 0.f, a11 = 0.f;
#pragma unroll
                for (int mg = 0; mg < 4; mg++) {
#pragma unroll
                    for (int rs = 0; rs < 2; rs++) {
                        int m = mg * 16 + g + 8 * rs;
                        int j = m + (m >= i_atom);
                        float2 xl0, xl1;
                        if (m != 63) {
                            xl0 = *(float2*)&Xl[j * LDA + cb * 16 + 2 * tig];
                            xl1 = *(float2*)&Xl[j * LDA + cb * 16 + 8 + 2 * tig];
                        } else {
                            xl0 = make_float2(0.f, 0.f);
                            xl1 = make_float2(0.f, 0.f);
                        }
                        a00 = fmaf(fast_tanh(D[mg][0][2 * rs]     + bb0.x), xl0.x, a00);
                        a01 = fmaf(fast_tanh(D[mg][0][2 * rs + 1] + bb0.y), xl0.y, a01);
                        a10 = fmaf(fast_tanh(D[mg][1][2 * rs]     + bb1.x), xl1.x, a10);
                        a11 = fmaf(fast_tanh(D[mg][1][2 * rs + 1] + bb1.y), xl1.y, a11);
                    }
                }
#pragma unroll
                for (int mk = 4; mk <= 16; mk <<= 1) {
                    a00 += __shfl_xor_sync(0xffffffffu, a00, mk);
                    a01 += __shfl_xor_sync(0xffffffffu, a01, mk);
                    a10 += __shfl_xor_sync(0xffffffffu, a10, mk);
                    a11 += __shfl_xor_sync(0xffffffffu, a11, mk);
                }
                if (g == 0) {
                    *(float2*)&vs[i_atom * LDX + cb * 16 + 2 * tig] =
                        make_float2(a00, a01);
                    *(float2*)&vs[i_atom * LDX + cb * 16 + 8 + 2 * tig] =
                        make_float2(a10, a11);
                }
            }
            __syncthreads();   // A dead; vs written; next fill safe
        }

        // v = tanh(vs@Wv1+b); X += v@Wv2+b  (scalar path, scratch in A region)
        pack_w(Wv1_g + wofs, WPA, tid);
        pack_w(Wv2_g + wofs, WPB, tid);
        __syncthreads();
        gemm2<1>(vs, LDX, WPA, bv1_g + bofs, tmpV, LDX, tid);
        __syncthreads();
        gemm2<2>(tmpV, LDX, WPB, bv2_g + bofs, X, LDX, tid);
        __syncthreads();
    }

    // ---- output head ----
    {
        float* Wah  = sm + OFF_A;
        float* Wbh  = sm + OFF_A + 2048;
        float* redh = sm + OFF_A + 4096;
#pragma unroll
        for (int ii = 0; ii < 4; ii++) Wah[tid + 512 * ii] = __ldg(W1_g + tid + 512 * ii);
        if (tid < 32) {
            Wbh[tid]      = __ldg(W2_g + tid);
            Wbh[32 + tid] = __ldg(b1_g + tid);
        }
        if (tid == 0) Wbh[64] = __ldg(b2_g);
        __syncthreads();

        int a = tid >> 3, cq = (tid & 7) * 4;
        float acc0 = Wbh[32 + cq + 0], acc1 = Wbh[32 + cq + 1];
        float acc2 = Wbh[32 + cq + 2], acc3 = Wbh[32 + cq + 3];
#pragma unroll 8
        for (int k = 0; k < 64; k++) {
            float xa = X[a * LDX + k];
            const float* wr = Wah + k * 32 + cq;
            acc0 = fmaf(xa, wr[0], acc0);
            acc1 = fmaf(xa, wr[1], acc1);
            acc2 = fmaf(xa, wr[2], acc2);
            acc3 = fmaf(xa, wr[3], acc3);
        }
        float s = fast_tanh(acc0) * Wbh[cq + 0] + fast_tanh(acc1) * Wbh[cq + 1] +
                  fast_tanh(acc2) * Wbh[cq + 2] + fast_tanh(acc3) * Wbh[cq + 3];
#pragma unroll
        for (int off = 16; off > 0; off >>= 1)
            s += __shfl_xor_sync(0xffffffffu, s, off);
        if (lane == 0) redh[wid] = s;
        __syncthreads();
        if (tid == 0) {
            float tot = 0.0f;
#pragma unroll
            for (int w = 0; w < 16; w++) tot += redh[w];
            out_g[b] = tot + 64.0f * Wbh[64];
        }
    }
}

extern "C" void kernel_launch(void* const* d_in, const int* in_sizes, int n_in,
                              void* d_out, int out_size) {
    const float* r_g   = (const float*)d_in[0];
    const float* v1_g  = (const float*)d_in[1];
    const float* v2_g  = (const float*)d_in[2];
    const float* cen_g = (const float*)d_in[3];
    const float* Wx_g  = (const float*)d_in[4];
    const float* bx_g  = (const float*)d_in[5];
    const float* Wf1_g = (const float*)d_in[6];
    const float* bf1_g = (const float*)d_in[7];
    const float* Wf2_g = (const float*)d_in[8];
    const float* bf2_g = (const float*)d_in[9];
    const float* Wv1_g = (const float*)d_in[10];
    const float* bv1_g = (const float*)d_in[11];
    const float* Wv2_g = (const float*)d_in[12];
    const float* bv2_g = (const float*)d_in[13];
    const float* W1_g  = (const float*)d_in[14];
    const float* b1_g  = (const float*)d_in[15];
    const float* W2_g  = (const float*)d_in[16];
    const float* b2_g  = (const float*)d_in[17];
    float* out = (float*)d_out;
    int batch = in_sizes[0] / 192;

    cudaFuncSetAttribute(schnet_kernel,
                         cudaFuncAttributeMaxDynamicSharedMemorySize, SMEM_BYTES);
    schnet_kernel<<<batch, 512, SMEM_BYTES>>>(
        r_g, v1_g, v2_g, cen_g, Wx_g, bx_g, Wf1_g, bf1_g, Wf2_g, bf2_g,
        Wv1_g, bv1_g, Wv2_g, bv2_g, W1_g, b1_g, W2_g, b2_g, out);
}

// round 6
// speedup vs baseline: 2.5563x; 1.0277x over previous
#include <cuda_runtime.h>
#include <cstdint>

// ---------------------------------------------------------------------------
// SchNet fused kernel, round 6: HMMA tf32 + per-row-block named barriers.
// Each row-block (4 warps / 128 threads) owns one atom per tile and its own
// 64-row A slice -> tile loop uses bar.sync(rb+1, 128) only; row-blocks
// pipeline independently. Pairwise-rcp tanh cuts MUFU 4->3 per 2 values.
// ---------------------------------------------------------------------------

typedef unsigned long long u64;
typedef unsigned int u32;

#define LDA 72   // A-tile / Wt row stride (floats)
#define LDX 68   // X / vs / tmpV stride (scalar path)

// float offsets
#define OFF_POS   0        // 192 (pad 256)
#define OFF_BIAS  256      // 128: bf1[64], bf2[64]
#define OFF_XL    384      // 64*72 = 4608
#define OFF_X     4992     // 64*68 = 4352
#define OFF_VS    9344     // 4352
#define OFF_WT1   13696    // 64*72 = 4608
#define OFF_WT2   18304    // 4608
#define OFF_A     22912    // 256*72 = 18432
#define SMEM_FLOATS 41344
#define SMEM_BYTES  (SMEM_FLOATS * 4)   // 165376

#define BAR_RB(id) asm volatile("bar.sync %0, 128;" :: "r"(id) : "memory")

__device__ __forceinline__ float fast_tanh(float x) {
    float e = __expf(2.0f * x);
    return 1.0f - __fdividef(2.0f, e + 1.0f);
}
// two tanh sharing one rcp: 3 MUFU per pair
__device__ __forceinline__ float2 tanh2(float a, float b) {
    float ya = fminf(a * 2.885390082f, 57.7f);
    float yb = fminf(b * 2.885390082f, 57.7f);
    float ta, tb, rp;
    asm("ex2.approx.f32 %0, %1;" : "=f"(ta) : "f"(ya));
    asm("ex2.approx.f32 %0, %1;" : "=f"(tb) : "f"(yb));
    float pa = ta + 1.0f, pb = tb + 1.0f;
    asm("rcp.approx.f32 %0, %1;" : "=f"(rp) : "f"(pa * pb));
    return make_float2(fmaf(-2.0f * pb, rp, 1.0f), fmaf(-2.0f * pa, rp, 1.0f));
}
__device__ __forceinline__ float tf32r(float f) {
    u32 v; asm("cvt.rna.tf32.f32 %0, %1;" : "=r"(v) : "f"(f));
    return __uint_as_float(v);
}
// k-mod-4 interleaved column offset: offs = {0,16,36,52}[k&3]
__device__ __forceinline__ int koffs(int km4) {
    return (km4 & 1) * 16 + (km4 & 2) * 18;
}

// ---------------------------------------------------------------------------
// Warp MMA block: D[4][2][4] = A(64 rows x 64k, perm, stride 72) @ Wt(16 cols)
// ---------------------------------------------------------------------------
__device__ __forceinline__ void mma_block(const float* __restrict__ Ap, int row0,
                                          const float* __restrict__ Wtp,
                                          float (&D)[4][2][4], int g, int tig) {
    const int offt = koffs(tig);
    float Bf[2][16];
#pragma unroll
    for (int nb = 0; nb < 2; nb++) {
        const float* bp = Wtp + (nb * 8 + g) * LDA + offt;
#pragma unroll
        for (int q = 0; q < 4; q++)
            *(float4*)&Bf[nb][4 * q] = *(const float4*)(bp + 4 * q);
    }
#pragma unroll
    for (int mg = 0; mg < 4; mg++) {
#pragma unroll
        for (int nb = 0; nb < 2; nb++)
#pragma unroll
            for (int i = 0; i < 4; i++) D[mg][nb][i] = 0.0f;
        float Aa[16], Ab[16];
        const float* ap = Ap + (row0 + mg * 16 + g) * LDA + offt;
#pragma unroll
        for (int q = 0; q < 4; q++) {
            *(float4*)&Aa[4 * q] = *(const float4*)(ap + 4 * q);
            *(float4*)&Ab[4 * q] = *(const float4*)(ap + 8 * LDA + 4 * q);
        }
#pragma unroll
        for (int s = 0; s < 8; s++) {
            u32 a0 = __float_as_uint(Aa[2 * s]);
            u32 a2 = __float_as_uint(Aa[2 * s + 1]);
            u32 a1 = __float_as_uint(Ab[2 * s]);
            u32 a3 = __float_as_uint(Ab[2 * s + 1]);
#pragma unroll
            for (int nb = 0; nb < 2; nb++) {
                u32 b0 = __float_as_uint(Bf[nb][2 * s]);
                u32 b1 = __float_as_uint(Bf[nb][2 * s + 1]);
                asm("mma.sync.aligned.m16n8k8.row.col.f32.tf32.tf32.f32 "
                    "{%0,%1,%2,%3}, {%4,%5,%6,%7}, {%8,%9}, {%0,%1,%2,%3};"
                    : "+f"(D[mg][nb][0]), "+f"(D[mg][nb][1]),
                      "+f"(D[mg][nb][2]), "+f"(D[mg][nb][3])
                    : "r"(a0), "r"(a1), "r"(a2), "r"(a3), "r"(b0), "r"(b1));
            }
        }
    }
}

// W[k][n] (64x64 row-major, global) -> Wt_perm[n][pos(k)] tf32, stride 72
__device__ __forceinline__ void store_wT(const float* __restrict__ g,
                                         float* __restrict__ s, int tid) {
#pragma unroll
    for (int ii = 0; ii < 8; ii++) {
        int idx = tid + ii * 512;
        int k = idx >> 6, n = idx & 63;
        s[n * LDA + koffs(k & 3) + (k >> 2)] = tf32r(__ldg(g + idx));
    }
}

// ---- scalar FFMA2 machinery for small 64x64 GEMMs ----
__device__ __forceinline__ void ffma2(u64& d, u64 a, u64 b) {
    asm("fma.rn.f32x2 %0, %1, %2, %0;" : "+l"(d) : "l"(a), "l"(b));
}
__device__ __forceinline__ void unpack2(u64 v, float& lo, float& hi) {
    asm("mov.b64 {%0, %1}, %2;" : "=f"(lo), "=f"(hi) : "l"(v));
}
__device__ __forceinline__ void pack_w(const float* __restrict__ g,
                                       float* __restrict__ s, int tid) {
#pragma unroll
    for (int ii = 0; ii < 8; ii++) {
        int idx = tid + ii * 512;
        int k = idx >> 6, c = idx & 63;
        int p = c >> 1, cl = c & 1;
        int pos = (p & ~3) | (((p & 3) + ((p >> 3) & 3)) & 3);
        s[(k >> 1) * 128 + pos * 4 + cl * 2 + (k & 1)] = __ldg(g + idx);
    }
}
template <int EPI>
__device__ __forceinline__ void gemm2(const float* __restrict__ A, int lda,
                                      const float* __restrict__ Wp,
                                      const float* __restrict__ bias,
                                      float* __restrict__ C, int ldc, int tid) {
    const int rg = tid >> 3, cg = tid & 7, c0 = cg << 3, x = (cg >> 1) & 3;
    const int u0 = (4 * cg + ((0 + x) & 3)) << 2;
    const int u1 = (4 * cg + ((1 + x) & 3)) << 2;
    const int u2 = (4 * cg + ((2 + x) & 3)) << 2;
    const int u3 = (4 * cg + ((3 + x) & 3)) << 2;
    const float* arow = A + rg * lda;
    u64 acc[8];
#pragma unroll
    for (int c = 0; c < 8; c++) acc[c] = 0ULL;
    const float* wk = Wp;
#pragma unroll 8
    for (int k2 = 0; k2 < 32; k2++) {
        ulonglong2 v0 = *(const ulonglong2*)(wk + u0);
        ulonglong2 v1 = *(const ulonglong2*)(wk + u1);
        ulonglong2 v2 = *(const ulonglong2*)(wk + u2);
        ulonglong2 v3 = *(const ulonglong2*)(wk + u3);
        u64 av = *(const u64*)(arow + 2 * k2);
        ffma2(acc[0], av, v0.x); ffma2(acc[1], av, v0.y);
        ffma2(acc[2], av, v1.x); ffma2(acc[3], av, v1.y);
        ffma2(acc[4], av, v2.x); ffma2(acc[5], av, v2.y);
        ffma2(acc[6], av, v3.x); ffma2(acc[7], av, v3.y);
        wk += 128;
    }
    const float4* bp = (const float4*)(bias + c0);
    float4 bA = __ldg(bp), bB = __ldg(bp + 1);
    float b8[8] = {bA.x, bA.y, bA.z, bA.w, bB.x, bB.y, bB.z, bB.w};
    float* cp = C + rg * ldc + c0;
    float o[8];
#pragma unroll
    for (int c = 0; c < 8; c++) {
        float lo, hi; unpack2(acc[c], lo, hi);
        float v = lo + hi + b8[c];
        if (EPI == 1) v = fast_tanh(v);
        o[c] = v;
    }
    if (EPI == 2) {
        float4 e0 = *(float4*)cp, e1 = *(float4*)(cp + 4);
        o[0] += e0.x; o[1] += e0.y; o[2] += e0.z; o[3] += e0.w;
        o[4] += e1.x; o[5] += e1.y; o[6] += e1.z; o[7] += e1.w;
    }
    *(float4*)cp       = make_float4(o[0], o[1], o[2], o[3]);
    *(float4*)(cp + 4) = make_float4(o[4], o[5], o[6], o[7]);
}

__global__ void __launch_bounds__(512, 1)
schnet_kernel(const float* __restrict__ r_g, const float* __restrict__ v1_g,
              const float* __restrict__ v2_g, const float* __restrict__ cen_g,
              const float* __restrict__ Wx_g,  const float* __restrict__ bx_g,
              const float* __restrict__ Wf1_g, const float* __restrict__ bf1_g,
              const float* __restrict__ Wf2_g, const float* __restrict__ bf2_g,
              const float* __restrict__ Wv1_g, const float* __restrict__ bv1_g,
              const float* __restrict__ Wv2_g, const float* __restrict__ bv2_g,
              const float* __restrict__ W1_g,  const float* __restrict__ b1_g,
              const float* __restrict__ W2_g,  const float* __restrict__ b2_g,
              float* __restrict__ out_g) {
    extern __shared__ float sm[];
    float* pos    = sm + OFF_POS;
    float* bias_s = sm + OFF_BIAS;
    float* Xl     = sm + OFF_XL;
    float* X      = sm + OFF_X;
    float* vs     = sm + OFF_VS;
    float* Wt1    = sm + OFF_WT1;
    float* Wt2    = sm + OFF_WT2;
    float* Ap     = sm + OFF_A;
    float* WPA    = sm + OFF_A;          // scalar scratch (A region reuse)
    float* WPB    = sm + OFF_A + 4096;
    float* tmpV   = sm + OFF_A + 8192;

    const int tid  = threadIdx.x, b = blockIdx.x;
    const int wid  = tid >> 5, lane = tid & 31;
    const int rb   = wid >> 2, cb = wid & 3;     // row-block(atom), col-block
    const int g    = lane >> 2, tig = lane & 3;
    const int rb_tid = tid & 127;                // thread-in-row-block
    const int bar_id = rb + 1;

    // ---- init ----
    if (tid < 192) pos[tid] = r_g[b * 192 + tid];
#pragma unroll
    for (int ii = 0; ii < 8; ii++) {
        int idx = tid + ii * 512;
        int a = idx >> 6, f = idx & 63;
        X[a * LDX + f] = (a < 2) ? __ldg(v1_g + f) : __ldg(v2_g + f);
    }
    __syncthreads();

    float D[4][2][4];

    for (int t = 0; t < 3; t++) {
        const int wofs = t * 4096, bofs = t * 64;

        // stage weights: Wx (scalar packed), Wf1/Wf2 (tf32 perm), biases
        pack_w(Wx_g + wofs, WPA, tid);
        store_wT(Wf1_g + wofs, Wt1, tid);
        store_wT(Wf2_g + wofs, Wt2, tid);
        if (tid < 64) {
            bias_s[tid]      = __ldg(bf1_g + bofs + tid);
            bias_s[64 + tid] = __ldg(bf2_g + bofs + tid);
        }
        __syncthreads();
        gemm2<0>(X, LDX, WPA, bx_g + bofs, Xl, LDA, tid);  // Xl = X@Wx+bx
        __syncthreads();

        const float* Wt1w = Wt1 + cb * 16 * LDA;
        const float* Wt2w = Wt2 + cb * 16 * LDA;

        // ---- 16 tiles x 1 atom per row-block; only 128-thread barriers ----
        for (int tt = 0; tt < 16; tt++) {
            const int i_atom = 4 * tt + rb;

            // rbf fill: rb's warps fill rb's 64-row slice (m=63 pad row)
            {
                int m = rb_tid >> 1, half = rb_tid & 1;
                float* arow = Ap + (rb * 64 + m) * LDA;
                if (m < 63) {
                    int j = m + (m >= i_atom);
                    float dx = pos[3 * i_atom + 0] - pos[3 * j + 0];
                    float dy = pos[3 * i_atom + 1] - pos[3 * j + 1];
                    float dz = pos[3 * i_atom + 2] - pos[3 * j + 2];
                    float dd = sqrtf(fmaf(dx, dx, fmaf(dy, dy, dz * dz)));
#pragma unroll
                    for (int h = 0; h < 2; h++) {
                        int km4 = 2 * half + h;
                        float* grp = arow + koffs(km4);
                        float cbase = dd - (float)km4 * 0.15625f;
#pragma unroll
                        for (int q = 0; q < 4; q++) {
                            float u0 = cbase - (float)(4 * q + 0) * 0.625f;
                            float u1 = cbase - (float)(4 * q + 1) * 0.625f;
                            float u2 = cbase - (float)(4 * q + 2) * 0.625f;
                            float u3 = cbase - (float)(4 * q + 3) * 0.625f;
                            float4 v;
                            v.x = tf32r(__expf(-10.0f * u0 * u0));
                            v.y = tf32r(__expf(-10.0f * u1 * u1));
                            v.z = tf32r(__expf(-10.0f * u2 * u2));
                            v.w = tf32r(__expf(-10.0f * u3 * u3));
                            *(float4*)(grp + 4 * q) = v;
                        }
                    }
                } else {
                    float4 z = make_float4(0.f, 0.f, 0.f, 0.f);
#pragma unroll
                    for (int h = 0; h < 2; h++) {
                        float* grp = arow + koffs(2 * half + h);
#pragma unroll
                        for (int q = 0; q < 4; q++) *(float4*)(grp + 4 * q) = z;
                    }
                }
            }
            BAR_RB(bar_id);

            // GEMM1: D = rbf @ Wf1^T
            mma_block(Ap, rb * 64, Wt1w, D, g, tig);
            BAR_RB(bar_id);   // all A reads done before epi1 overwrites

            // epilogue1: h1 = tanh(D + bf1) -> A (perm, tf32)
            {
                const int idxb = cb * 4 + (tig >> 1);
                const int p0 = (tig & 1) * 36;
#pragma unroll
                for (int nb = 0; nb < 2; nb++) {
                    float2 bb = *(float2*)&bias_s[cb * 16 + nb * 8 + 2 * tig];
                    int pa = p0 + idxb + 2 * nb;
#pragma unroll
                    for (int mg = 0; mg < 4; mg++) {
                        float* r0p = Ap + (rb * 64 + mg * 16 + g) * LDA;
                        float* r1p = r0p + 8 * LDA;
                        float2 t01 = tanh2(D[mg][nb][0] + bb.x, D[mg][nb][1] + bb.y);
                        float2 t23 = tanh2(D[mg][nb][2] + bb.x, D[mg][nb][3] + bb.y);
                        r0p[pa]      = tf32r(t01.x);
                        r0p[pa + 16] = tf32r(t01.y);
                        r1p[pa]      = tf32r(t23.x);
                        r1p[pa + 16] = tf32r(t23.y);
                    }
                }
            }
            BAR_RB(bar_id);

            // GEMM2: D = h1 @ Wf2^T
            mma_block(Ap, rb * 64, Wt2w, D, g, tig);
            BAR_RB(bar_id);   // A reads done; next fill may overwrite

            // epilogue2: h2 = tanh(D + bf2); cfconv vs[i][c] = sum_m h2*Xl[j]
            {
                float2 bb0 = *(float2*)&bias_s[64 + cb * 16 + 2 * tig];
                float2 bb1 = *(float2*)&bias_s[64 + cb * 16 + 8 + 2 * tig];
                float a00 = 0.f, a01 = 0.f, a10 = 0.f, a11 = 0.f;
#pragma unroll
                for (int mg = 0; mg < 4; mg++) {
#pragma unroll
                    for (int rs = 0; rs < 2; rs++) {
                        int m = mg * 16 + g + 8 * rs;
                        int j = m + (m >= i_atom);
                        float2 xl0, xl1;
                        if (m != 63) {
                            xl0 = *(float2*)&Xl[j * LDA + cb * 16 + 2 * tig];
                            xl1 = *(float2*)&Xl[j * LDA + cb * 16 + 8 + 2 * tig];
                        } else {
                            xl0 = make_float2(0.f, 0.f);
                            xl1 = make_float2(0.f, 0.f);
                        }
                        float2 t0 = tanh2(D[mg][0][2 * rs] + bb0.x,
                                          D[mg][0][2 * rs + 1] + bb0.y);
                        float2 t1 = tanh2(D[mg][1][2 * rs] + bb1.x,
                                          D[mg][1][2 * rs + 1] + bb1.y);
                        a00 = fmaf(t0.x, xl0.x, a00);
                        a01 = fmaf(t0.y, xl0.y, a01);
                        a10 = fmaf(t1.x, xl1.x, a10);
                        a11 = fmaf(t1.y, xl1.y, a11);
                    }
                }
#pragma unroll
                for (int mk = 4; mk <= 16; mk <<= 1) {
                    a00 += __shfl_xor_sync(0xffffffffu, a00, mk);
                    a01 += __shfl_xor_sync(0xffffffffu, a01, mk);
                    a10 += __shfl_xor_sync(0xffffffffu, a10, mk);
                    a11 += __shfl_xor_sync(0xffffffffu, a11, mk);
                }
                if (g == 0) {
                    *(float2*)&vs[i_atom * LDX + cb * 16 + 2 * tig] =
                        make_float2(a00, a01);
                    *(float2*)&vs[i_atom * LDX + cb * 16 + 8 + 2 * tig] =
                        make_float2(a10, a11);
                }
            }
            // no barrier needed: next fill only writes rb's own A slice, and
            // the post-GEMM2 barrier already ordered A reads vs this thread.
        }
        __syncthreads();

        // v = tanh(vs@Wv1+b); X += v@Wv2+b  (scalar path, scratch in A region)
        pack_w(Wv1_g + wofs, WPA, tid);
        pack_w(Wv2_g + wofs, WPB, tid);
        __syncthreads();
        gemm2<1>(vs, LDX, WPA, bv1_g + bofs, tmpV, LDX, tid);
        __syncthreads();
        gemm2<2>(tmpV, LDX, WPB, bv2_g + bofs, X, LDX, tid);
        __syncthreads();
    }

    // ---- output head ----
    {
        float* Wah  = sm + OFF_A;
        float* Wbh  = sm + OFF_A + 2048;
        float* redh = sm + OFF_A + 4096;
#pragma unroll
        for (int ii = 0; ii < 4; ii++) Wah[tid + 512 * ii] = __ldg(W1_g + tid + 512 * ii);
        if (tid < 32) {
            Wbh[tid]      = __ldg(W2_g + tid);
            Wbh[32 + tid] = __ldg(b1_g + tid);
        }
        if (tid == 0) Wbh[64] = __ldg(b2_g);
        __syncthreads();

        int a = tid >> 3, cq = (tid & 7) * 4;
        float acc0 = Wbh[32 + cq + 0], acc1 = Wbh[32 + cq + 1];
        float acc2 = Wbh[32 + cq + 2], acc3 = Wbh[32 + cq + 3];
#pragma unroll 8
        for (int k = 0; k < 64; k++) {
            float xa = X[a * LDX + k];
            const float* wr = Wah + k * 32 + cq;
            acc0 = fmaf(xa, wr[0], acc0);
            acc1 = fmaf(xa, wr[1], acc1);
            acc2 = fmaf(xa, wr[2], acc2);
            acc3 = fmaf(xa, wr[3], acc3);
        }
        float s = fast_tanh(acc0) * Wbh[cq + 0] + fast_tanh(acc1) * Wbh[cq + 1] +
                  fast_tanh(acc2) * Wbh[cq + 2] + fast_tanh(acc3) * Wbh[cq + 3];
#pragma unroll
        for (int off = 16; off > 0; off >>= 1)
            s += __shfl_xor_sync(0xffffffffu, s, off);
        if (lane == 0) redh[wid] = s;
        __syncthreads();
        if (tid == 0) {
            float tot = 0.0f;
#pragma unroll
            for (int w = 0; w < 16; w++) tot += redh[w];
            out_g[b] = tot + 64.0f * Wbh[64];
        }
    }
}

extern "C" void kernel_launch(void* const* d_in, const int* in_sizes, int n_in,
                              void* d_out, int out_size) {
    const float* r_g   = (const float*)d_in[0];
    const float* v1_g  = (const float*)d_in[1];
    const float* v2_g  = (const float*)d_in[2];
    const float* cen_g = (const float*)d_in[3];
    const float* Wx_g  = (const float*)d_in[4];
    const float* bx_g  = (const float*)d_in[5];
    const float* Wf1_g = (const float*)d_in[6];
    const float* bf1_g = (const float*)d_in[7];
    const float* Wf2_g = (const float*)d_in[8];
    const float* bf2_g = (const float*)d_in[9];
    const float* Wv1_g = (const float*)d_in[10];
    const float* bv1_g = (const float*)d_in[11];
    const float* Wv2_g = (const float*)d_in[12];
    const float* bv2_g = (const float*)d_in[13];
    const float* W1_g  = (const float*)d_in[14];
    const float* b1_g  = (const float*)d_in[15];
    const float* W2_g  = (const float*)d_in[16];
    const float* b2_g  = (const float*)d_in[17];
    float* out = (float*)d_out;
    int batch = in_sizes[0] / 192;

    cudaFuncSetAttribute(schnet_kernel,
                         cudaFuncAttributeMaxDynamicSharedMemorySize, SMEM_BYTES);
    schnet_kernel<<<batch, 512, SMEM_BYTES>>>(
        r_g, v1_g, v2_g, cen_g, Wx_g, bx_g, Wf1_g, bf1_g, Wf2_g, bf2_g,
        Wv1_g, bv1_g, Wv2_g, bv2_g, W1_g, b1_g, W2_g, b2_g, out);
}